// round 17
// baseline (speedup 1.0000x reference)
#include <cuda_runtime.h>
#include <cuda_fp16.h>
#include <cstdint>
#include <math.h>

#define BS   8
#define NT   128
#define CH   1024
#define KH   4
#define HID  512
#define GD   2048
#define NGRP 8
#define MM   1024

// ---- static device scratch ----
__device__ float4 g_Wa[8u*128*128*32];        // Wih frag-packed tf32 (67MB)
__device__ uint4  g_Wp[1024u*32*32];          // Whh unit-frag-packed fp16 (16.8MB)
__device__ float2 g_Xp[4u*128*128*32];        // inputs frag-packed tf32 (16.8MB)
__device__ float2 g_gates[(size_t)NGRP*GD*512]; // [grp][grow][m/2] fp32 (67MB)
__device__ uint2  g_hbuf[129u*NGRP*1024];     // [t][grp][s32][l32] h fp16 B-frags (8.4MB)

// ---- helpers ----
__device__ __forceinline__ uint32_t f2tf(float x) {
    uint32_t r; asm("cvt.rna.tf32.f32 %0, %1;" : "=r"(r) : "f"(x)); return r;
}
__device__ __forceinline__ uint32_t pack2h(float a, float b) {
    __half2 h = __floats2half2_rn(a, b);          // a -> low, b -> high
    return *(uint32_t*)&h;
}
__device__ __forceinline__ void mma_tf32(float& c0, float& c1, float& c2, float& c3,
                                         uint32_t a0, uint32_t a1, uint32_t a2, uint32_t a3,
                                         uint32_t b0, uint32_t b1) {
    asm volatile("mma.sync.aligned.m16n8k8.row.col.f32.tf32.tf32.f32 "
        "{%0,%1,%2,%3}, {%4,%5,%6,%7}, {%8,%9}, {%0,%1,%2,%3};\n"
        : "+f"(c0), "+f"(c1), "+f"(c2), "+f"(c3)
        : "r"(a0), "r"(a1), "r"(a2), "r"(a3), "r"(b0), "r"(b1));
}
__device__ __forceinline__ void mma_f16(float& c0, float& c1, float& c2, float& c3,
                                        uint32_t a0, uint32_t a1, uint32_t a2, uint32_t a3,
                                        uint32_t b0, uint32_t b1) {
    asm volatile("mma.sync.aligned.m16n8k16.row.col.f32.f16.f16.f32 "
        "{%0,%1,%2,%3}, {%4,%5,%6,%7}, {%8,%9}, {%0,%1,%2,%3};\n"
        : "+f"(c0), "+f"(c1), "+f"(c2), "+f"(c3)
        : "r"(a0), "r"(a1), "r"(a2), "r"(a3), "r"(b0), "r"(b1));
}
__device__ __forceinline__ float sigm(float x) { return 1.f / (1.f + __expf(-x)); }
__device__ __forceinline__ float tanh_f(float x) { return 2.f / (1.f + __expf(-2.f * x)) - 1.f; }

// ---------------------------------------------------------------------------
// Merged: h init + input B-frag pack (launch #0)
__global__ void setup_kernel(const float* __restrict__ in) {
    int idx = blockIdx.x * blockDim.x + threadIdx.x;
    if (idx < NGRP * 1024) g_hbuf[idx] = make_uint2(0u, 0u);   // h(t=0) = 0 (fp16)

    if (idx >= BS * NT * CH) return;
    int c  = idx % CH;
    int bt = idx / CH;
    int t  = bt % NT;
    int b  = bt / NT;
    float4 v = ((const float4*)in)[idx];
    int m = t * BS + b;
    int mblk = m >> 3, s = c >> 3;
    int l = ((m & 7) << 2) | (c & 3);
    int half = (c >> 2) & 1;
    float* xp = (float*)g_Xp;
    float vv[4] = {v.x, v.y, v.z, v.w};
#pragma unroll
    for (int kk = 0; kk < 4; kk++) {
        size_t fi = ((((size_t)kk * 128 + mblk) * 128 + s) * 32 + l) * 2 + half;
        xp[fi] = __uint_as_float(f2tf(vv[kk]));
    }
}

// ---------------------------------------------------------------------------
// Merged: Wih tf32 A-frag pack + Whh fp16 unit-frag pack (launch #1)
#define NWIH (8*128*128*32)
#define NWP  (1024*32*32)
__global__ void prepack_all(const float* __restrict__ Wih_f, const float* __restrict__ Wih_b,
                            const float* __restrict__ Whh_f, const float* __restrict__ Whh_b) {
    int t = blockIdx.x * blockDim.x + threadIdx.x;
    if (t < NWIH) {
        int l = t & 31, s = (t >> 5) & 127, g16 = (t >> 12) & 127, grp = t >> 19;
        int dir = grp >> 2, kh = grp & 3;
        const float* W = (dir ? Wih_b : Wih_f) + (size_t)kh * GD * CH;
        int r = g16 * 16 + (l >> 2);
        int c = s * 8 + (l & 3);
        float4 v;
        v.x = __uint_as_float(f2tf(W[(size_t)r * CH + c]));
        v.y = __uint_as_float(f2tf(W[(size_t)(r + 8) * CH + c]));
        v.z = __uint_as_float(f2tf(W[(size_t)r * CH + c + 4]));
        v.w = __uint_as_float(f2tf(W[(size_t)(r + 8) * CH + c + 4]));
        g_Wa[t] = v;
    } else {
        int q = t - NWIH;
        if (q >= NWP) return;
        // fp16 A-frag for m16n8k16: unit = grp*128+j4 (16 rows = 4 gates x 4 j),
        // s = k16-step (0..31), l = lane.
        int l = q & 31, s = (q >> 5) & 31, unit = q >> 10;
        int grp = unit >> 7, j4 = unit & 127;
        int dir = grp >> 2, kh = grp & 3;
        const float* W = (dir ? Whh_b : Whh_f) + (size_t)kh * GD * HID;
        int r = l >> 2;
        int grow0 = (r >> 2) * 512 + j4 * 4 + (r & 3);   // gates 0/1
        int grow1 = grow0 + 1024;                        // gates 2/3
        int k0 = s * 16 + (l & 3) * 2;
        uint4 v;
        v.x = pack2h(W[(size_t)grow0 * HID + k0],     W[(size_t)grow0 * HID + k0 + 1]);
        v.y = pack2h(W[(size_t)grow1 * HID + k0],     W[(size_t)grow1 * HID + k0 + 1]);
        v.z = pack2h(W[(size_t)grow0 * HID + k0 + 8], W[(size_t)grow0 * HID + k0 + 9]);
        v.w = pack2h(W[(size_t)grow1 * HID + k0 + 8], W[(size_t)grow1 * HID + k0 + 9]);
        g_Wp[(size_t)unit * 1024 + s * 32 + l] = v;
    }
}

// ---------------------------------------------------------------------------
// Input GEMM (launch #2): 3-stage cp.async smem pipeline (R15-proven).
#define GS_CHUNKS 3072
#define NIT 32

__device__ __forceinline__ void gemm_load_stage(
    int it, int stg, int grp, int kh, int by, int bx, int tid, uint4* sG)
{
    uint32_t sb = (uint32_t)__cvta_generic_to_shared(sG + stg * GS_CHUNKS);
    const uint4* Wa4 = (const uint4*)g_Wa;
#pragma unroll
    for (int e = 0; e < GS_CHUNKS / 256; e++) {
        int i = e * 256 + tid;
        const void* src;
        if (i < 1024) {
            int tile = i >> 7, off = i & 127;
            src = Wa4 + (((size_t)(grp * 128 + by * 8 + tile) * 128 + it * 4) * 32) + off;
        } else {
            int jj = i - 1024;
            int mblk = jj >> 6, off = jj & 63;
            src = (const float2*)g_Xp
                  + (((size_t)(kh * 128 + bx * 32 + mblk) * 128 + it * 4) * 32) + off * 2;
        }
        asm volatile("cp.async.cg.shared.global [%0], [%1], 16;\n"
                     :: "r"(sb + i * 16), "l"(src));
    }
    asm volatile("cp.async.commit_group;\n");
}

__global__ void __launch_bounds__(256) input_gemm(
    const float* __restrict__ bih_f, const float* __restrict__ bhh_f,
    const float* __restrict__ bih_b, const float* __restrict__ bhh_b)
{
    extern __shared__ uint4 sG[];
    int grp = blockIdx.z, dir = grp >> 2, kh = grp & 3;
    int by = blockIdx.y, bx = blockIdx.x;
    int tid = threadIdx.x, l = tid & 31, warp = tid >> 5;
    int wm = warp & 1, wn = warp >> 1;

    gemm_load_stage(0, 0, grp, kh, by, bx, tid, sG);
    gemm_load_stage(1, 1, grp, kh, by, bx, tid, sG);

    float acc[4][8][4];
#pragma unroll
    for (int i = 0; i < 4; i++)
#pragma unroll
        for (int j = 0; j < 8; j++)
#pragma unroll
            for (int e = 0; e < 4; e++) acc[i][j][e] = 0.f;

    for (int it = 0; it < NIT; it++) {
        if (it < NIT - 1) asm volatile("cp.async.wait_group 1;\n");
        else             asm volatile("cp.async.wait_group 0;\n");
        __syncthreads();
        if (it + 2 < NIT) gemm_load_stage(it + 2, (it + 2) % 3, grp, kh, by, bx, tid, sG);

        int stg = it % 3;
        const uint4*  sA = sG + stg * GS_CHUNKS;
        const float2* sB = (const float2*)(sG + stg * GS_CHUNKS + 1024);
#pragma unroll
        for (int s = 0; s < 4; s++) {
            uint4 aa[4];
            uint32_t b0[8], b1[8];
#pragma unroll
            for (int i = 0; i < 4; i++)
                aa[i] = sA[(wm * 4 + i) * 128 + s * 32 + l];
#pragma unroll
            for (int j = 0; j < 8; j++) {
                float2 bv = sB[(wn * 8 + j) * 128 + s * 32 + l];
                b0[j] = __float_as_uint(bv.x);
                b1[j] = __float_as_uint(bv.y);
            }
#pragma unroll
            for (int i = 0; i < 4; i++)
#pragma unroll
                for (int j = 0; j < 8; j++)
                    mma_tf32(acc[i][j][0], acc[i][j][1], acc[i][j][2], acc[i][j][3],
                             aa[i].x, aa[i].y, aa[i].z, aa[i].w, b0[j], b1[j]);
        }
        __syncthreads();
    }

    const float* bi = (dir ? bih_b : bih_f) + kh * GD;
    const float* bh = (dir ? bhh_b : bhh_f) + kh * GD;
#pragma unroll
    for (int i = 0; i < 4; i++) {
        int g16 = by * 8 + wm * 4 + i;
        int ra = g16 * 16 + (l >> 2), rb = ra + 8;
        float ba  = bi[ra] + bh[ra];
        float bbv = bi[rb] + bh[rb];
#pragma unroll
        for (int j = 0; j < 8; j++) {
            int mhalf = (bx * 32 + wn * 8 + j) * 4 + (l & 3);
            g_gates[((size_t)grp * GD + ra) * 512 + mhalf] =
                make_float2(acc[i][j][0] + ba, acc[i][j][1] + ba);
            g_gates[((size_t)grp * GD + rb) * 512 + mhalf] =
                make_float2(acc[i][j][2] + bbv, acc[i][j][3] + bbv);
        }
    }
}

// ---------------------------------------------------------------------------
// Persistent recurrent kernel (launch #3): 8 clusters x 16 CTAs, one cluster
// per (dir,head) group. fp16 weights in smem (8 units x 16KB). Per-step sync
// = barrier.cluster (arrive=release, wait=acquire, cluster scope). No global
// atomics, no threadfence. k-split warp pairs (chain 16 x m16n8k16).
__global__ void __launch_bounds__(512) __cluster_dims__(16, 1, 1)
lstm_persistent(float* __restrict__ out)
{
    extern __shared__ uint4 sW[];                 // 8192 uint4 = 128KB weights
    float4* sPart = (float4*)(sW + 8192);         // 8 x 32 float4 = 4KB

    int tid = threadIdx.x, l = tid & 31, w = tid >> 5;
    int cta  = blockIdx.x;
    int rank = cta & 15;
    int grp  = cta >> 4;
    int dir = grp >> 2, kh = grp & 3;
    int ustart = grp * 128 + rank * 8;

    // load this CTA's 8 weight units into smem
    {
        uint32_t sb = (uint32_t)__cvta_generic_to_shared(sW);
        const uint4* src = g_Wp + (size_t)ustart * 1024;
#pragma unroll
        for (int e = 0; e < 16; e++) {
            int i = e * 512 + tid;
            asm volatile("cp.async.cg.shared.global [%0], [%1], 16;\n"
                         :: "r"(sb + i * 16), "l"(src + i));
        }
        asm volatile("cp.async.commit_group;\n");
        asm volatile("cp.async.wait_group 0;\n");
    }
    __syncthreads();

    int uu = w >> 1, khalf = w & 1;
    int j4 = rank * 8 + uu;

    const uint4* wA = sW + uu * 1024 + khalf * 512 + l;   // 16 k16-steps, stride 32
    int r = l >> 2;
    int ga = (r >> 2) * 512 + j4 * 4 + (r & 3);
    const float2* ginA = g_gates + ((size_t)grp * GD + ga) * 512 + (l & 3);
    const float2* ginB = ginA + (size_t)1024 * 512;

    int jj = r & 3;               // lanes<16: local j
    int b0 = (l & 3) * 2;
    int j  = j4 * 4 + jj;
    // fp16 h-frag store coords for j: s16 = j>>4, jl = j&15
    int hs = j >> 4, jl = j & 15;
    int regsel = jl >> 3, lq = (jl & 7) >> 1, fpo = jl & 1;

    float cs0 = 0.f, cs1 = 0.f;

    for (int t = 0; t < NT; t++) {
        int tt = dir ? (NT - 1 - t) : t;
        float c0 = 0.f, c1 = 0.f, c2 = 0.f, c3 = 0.f;

        {
            const uint2* hrd = g_hbuf + ((size_t)t * NGRP + grp) * 1024
                               + khalf * 512 + l;
#pragma unroll
            for (int s = 0; s < 16; s++) {
                uint4 a = wA[s * 32];
                uint2 hv = __ldg(hrd + s * 32);
                mma_f16(c0, c1, c2, c3, a.x, a.y, a.z, a.w, hv.x, hv.y);
            }
            if (khalf) sPart[uu * 32 + l] = make_float4(c0, c1, c2, c3);
        }
        __syncthreads();   // partials visible block-wide

        if (khalf == 0) {
            float4 p = sPart[uu * 32 + l];
            float2 ia = __ldg(ginA + tt * 4);
            float2 ib = __ldg(ginB + tt * 4);
            c0 += p.x + ia.x;
            c1 += p.y + ia.y;
            c2 += p.z + ib.x;
            c3 += p.w + ib.y;

            float r0 = __shfl_xor_sync(0xffffffffu, c0, 16);
            float r1 = __shfl_xor_sync(0xffffffffu, c1, 16);
            float r2 = __shfl_xor_sync(0xffffffffu, c2, 16);
            float r3 = __shfl_xor_sync(0xffffffffu, c3, 16);

            if (l < 16) {
                float i0 = sigm(c0), f0 = sigm(r0), g0 = tanh_f(c2), o0 = sigm(r2);
                cs0 = f0 * cs0 + i0 * g0;
                float hn0 = o0 * tanh_f(cs0);
                float i1 = sigm(c1), f1 = sigm(r1), g1 = tanh_f(c3), o1 = sigm(r3);
                cs1 = f1 * cs1 + i1 * g1;
                float hn1 = o1 * tanh_f(cs1);

                // h(t+1) as fp16 B-frags: ushort idx = (s*32+lane)*4 + regsel*2 + fpo
                ushort* hb = (ushort*)(g_hbuf + ((size_t)(t + 1) * NGRP + grp) * 1024);
                int ui = (hs * 32 + (b0 * 4 + lq)) * 4 + regsel * 2 + fpo;
                hb[ui]      = __half_as_ushort(__float2half_rn(hn0));
                hb[ui + 16] = __half_as_ushort(__float2half_rn(hn1));   // batch b0+1 -> lane+4

                out[(((size_t)b0 * NT + tt) * (2 * HID) + dir * HID + j) * KH + kh] = hn0;
                out[(((size_t)(b0 + 1) * NT + tt) * (2 * HID) + dir * HID + j) * KH + kh] = hn1;
            }
        }

        if (t < NT - 1) {
            // cluster barrier: arrive(release) / wait(acquire) — orders the
            // global h stores above against next step's loads, cluster-wide.
            asm volatile("barrier.cluster.arrive.aligned;" ::: "memory");
            asm volatile("barrier.cluster.wait.aligned;" ::: "memory");
        }
    }
}

// ---------------------------------------------------------------------------
extern "C" void kernel_launch(void* const* d_in, const int* in_sizes, int n_in,
                              void* d_out, int out_size) {
    const float* inputs = (const float*)d_in[0];
    const float* Wih_f  = (const float*)d_in[1];
    const float* Whh_f  = (const float*)d_in[2];
    const float* bih_f  = (const float*)d_in[3];
    const float* bhh_f  = (const float*)d_in[4];
    const float* Wih_b  = (const float*)d_in[5];
    const float* Whh_b  = (const float*)d_in[6];
    const float* bih_b  = (const float*)d_in[7];
    const float* bhh_b  = (const float*)d_in[8];
    float* out = (float*)d_out;

    const int SMEM_PERS = 8192 * 16 + 8 * 32 * 16;   // 135168
    const int SMEM_GEMM = 3 * GS_CHUNKS * 16;        // 147456
    cudaFuncSetAttribute(lstm_persistent, cudaFuncAttributeMaxDynamicSharedMemorySize, SMEM_PERS);
    cudaFuncSetAttribute(lstm_persistent, cudaFuncAttributeNonPortableClusterSizeAllowed, 1);
    cudaFuncSetAttribute(input_gemm, cudaFuncAttributeMaxDynamicSharedMemorySize, SMEM_GEMM);

    setup_kernel<<<(BS * NT * CH + 255) / 256, 256>>>(inputs);
    prepack_all<<<(NWIH + NWP + 255) / 256, 256>>>(Wih_f, Wih_b, Whh_f, Whh_b);
    input_gemm<<<dim3(4, 16, 8), 256, SMEM_GEMM>>>(bih_f, bhh_f, bih_b, bhh_b);
    lstm_persistent<<<128, 512, SMEM_PERS>>>(out);
}